// round 5
// baseline (speedup 1.0000x reference)
#include <cuda_runtime.h>

typedef unsigned long long u64;
typedef unsigned int u32;

#define Bc 256
#define Tc 1024
#define Hc 128
#define Gc 512
#define Mc (Bc*Tc)

// Scratch (device globals: sanctioned workaround for the no-alloc rule)
__device__ float g_xg[(size_t)Mc * Gc];   // [B*T, 512] gate preactivations
__device__ float g_h0s[(size_t)Mc * Hc];  // [B*T, 128] layer-0 hidden states

// ---------- packed f32x2 helpers ----------
static __device__ __forceinline__ u64 ffma2(u64 a, u64 b, u64 c) {
    u64 d; asm("fma.rn.f32x2 %0, %1, %2, %3;" : "=l"(d) : "l"(a), "l"(b), "l"(c)); return d;
}
static __device__ __forceinline__ u64 fadd2(u64 a, u64 b) {
    u64 d; asm("add.rn.f32x2 %0, %1, %2;" : "=l"(d) : "l"(a), "l"(b)); return d;
}
static __device__ __forceinline__ u64 dup2(float v) {
    u64 d; asm("mov.b64 %0, {%1, %1};" : "=l"(d) : "f"(v)); return d;
}
static __device__ __forceinline__ float red2(u64 v) {
    u32 a, b; asm("mov.b64 {%0, %1}, %2;" : "=r"(a), "=r"(b) : "l"(v));
    return __uint_as_float(a) + __uint_as_float(b);
}
static __device__ __forceinline__ float sigf(float x) {
    return __fdividef(1.f, 1.f + __expf(-x));
}
static __device__ __forceinline__ float tanh_f(float x) {
    return 1.f - __fdividef(2.f, 1.f + __expf(2.f * x));
}

// ============================================================
// GEMM: out[m][n] = sum_k X[m][k]*W[n][k] + bias[n]
// M=262144, N=512, K in {64,128}. BM=128, BN=256, BK=16, dbl-buffered.
// 256 threads (tm=tid>>4, tn=tid&15); thread tile 8m x 16n.
// A dup'd in smem (u64 per m), B natural n-pairs (u64). 2B LDS / FFMA2.
// ============================================================
#define GBK 16
#define GEMM_SMEM (2*(GBK*128 + GBK*128)*8)   // 2 stages x (adup 16KB + b 16KB) = 64KB

__global__ __launch_bounds__(256, 1) void gemm_xw(
    const float* __restrict__ X, const float* __restrict__ W,
    const float* __restrict__ bias, float* __restrict__ out, int K)
{
    extern __shared__ u64 smg[];
    u64* adup = smg;                      // [2][16][128]  dup'd X
    u64* bsp  = smg + 2 * GBK * 128;      // [2][16][128]  B n-pairs (float view [16][256])

    const int tid = threadIdx.x;
    const int tn = tid & 15, tm = tid >> 4;
    const int mB = blockIdx.x * 128, nB = blockIdx.y * 256;
    const int S = K / GBK;

    float4 aR0, aR1, bR0, bR1, bR2, bR3;

#define LDG_STAGE(s) { \
    int fl0 = tid,       r0_ = fl0 >> 2, q0_ = fl0 & 3; \
    int fl1 = tid + 256, r1_ = fl1 >> 2, q1_ = fl1 & 3; \
    aR0 = *(const float4*)&X[(size_t)(mB + r0_) * K + (s) * GBK + q0_ * 4]; \
    aR1 = *(const float4*)&X[(size_t)(mB + r1_) * K + (s) * GBK + q1_ * 4]; \
    int n0_ = fl0 >> 2; \
    bR0 = *(const float4*)&W[(size_t)(nB + n0_) * K + (s) * GBK + q0_ * 4]; \
    int fn1 = tid + 256,  nn1 = fn1 >> 2, qn1 = fn1 & 3; \
    bR1 = *(const float4*)&W[(size_t)(nB + nn1) * K + (s) * GBK + qn1 * 4]; \
    int fn2 = tid + 512,  nn2 = fn2 >> 2, qn2 = fn2 & 3; \
    bR2 = *(const float4*)&W[(size_t)(nB + nn2) * K + (s) * GBK + qn2 * 4]; \
    int fn3 = tid + 768,  nn3 = fn3 >> 2, qn3 = fn3 & 3; \
    bR3 = *(const float4*)&W[(size_t)(nB + nn3) * K + (s) * GBK + qn3 * 4]; \
}

#define STS_STAGE(buf) { \
    u64* ad = adup + (buf) * GBK * 128; \
    float* bf = (float*)(bsp + (buf) * GBK * 128); \
    int fl0 = tid,       r0_ = fl0 >> 2, q0_ = fl0 & 3; \
    ad[(q0_*4+0)*128 + r0_] = dup2(aR0.x); ad[(q0_*4+1)*128 + r0_] = dup2(aR0.y); \
    ad[(q0_*4+2)*128 + r0_] = dup2(aR0.z); ad[(q0_*4+3)*128 + r0_] = dup2(aR0.w); \
    int fl1 = tid + 256, r1_ = fl1 >> 2, q1_ = fl1 & 3; \
    ad[(q1_*4+0)*128 + r1_] = dup2(aR1.x); ad[(q1_*4+1)*128 + r1_] = dup2(aR1.y); \
    ad[(q1_*4+2)*128 + r1_] = dup2(aR1.z); ad[(q1_*4+3)*128 + r1_] = dup2(aR1.w); \
    int n0_ = fl0 >> 2; \
    bf[(q0_*4+0)*256 + n0_] = bR0.x; bf[(q0_*4+1)*256 + n0_] = bR0.y; \
    bf[(q0_*4+2)*256 + n0_] = bR0.z; bf[(q0_*4+3)*256 + n0_] = bR0.w; \
    int fn1 = tid + 256, nn1 = fn1 >> 2, qn1 = fn1 & 3; \
    bf[(qn1*4+0)*256 + nn1] = bR1.x; bf[(qn1*4+1)*256 + nn1] = bR1.y; \
    bf[(qn1*4+2)*256 + nn1] = bR1.z; bf[(qn1*4+3)*256 + nn1] = bR1.w; \
    int fn2 = tid + 512, nn2 = fn2 >> 2, qn2 = fn2 & 3; \
    bf[(qn2*4+0)*256 + nn2] = bR2.x; bf[(qn2*4+1)*256 + nn2] = bR2.y; \
    bf[(qn2*4+2)*256 + nn2] = bR2.z; bf[(qn2*4+3)*256 + nn2] = bR2.w; \
    int fn3 = tid + 768, nn3 = fn3 >> 2, qn3 = fn3 & 3; \
    bf[(qn3*4+0)*256 + nn3] = bR3.x; bf[(qn3*4+1)*256 + nn3] = bR3.y; \
    bf[(qn3*4+2)*256 + nn3] = bR3.z; bf[(qn3*4+3)*256 + nn3] = bR3.w; \
}

    u64 acc[8][8];
#pragma unroll
    for (int i = 0; i < 8; i++)
#pragma unroll
        for (int j = 0; j < 8; j++) acc[i][j] = 0ull;

    LDG_STAGE(0);
    STS_STAGE(0);
    __syncthreads();

#pragma unroll 1
    for (int s = 0; s < S; s++) {
        int cb = s & 1;
        if (s + 1 < S) { LDG_STAGE(s + 1); }
        const u64* ad = adup + cb * GBK * 128 + tm * 8;
        const u64* bb = bsp  + cb * GBK * 128 + tn * 8;
#pragma unroll
        for (int k = 0; k < GBK; k++) {
            u64 A[8], B[8];
            {
                ulonglong2 x0 = *(const ulonglong2*)(ad + k * 128 + 0);
                ulonglong2 x1 = *(const ulonglong2*)(ad + k * 128 + 2);
                ulonglong2 x2 = *(const ulonglong2*)(ad + k * 128 + 4);
                ulonglong2 x3 = *(const ulonglong2*)(ad + k * 128 + 6);
                A[0]=x0.x; A[1]=x0.y; A[2]=x1.x; A[3]=x1.y;
                A[4]=x2.x; A[5]=x2.y; A[6]=x3.x; A[7]=x3.y;
                ulonglong2 y0 = *(const ulonglong2*)(bb + k * 128 + 0);
                ulonglong2 y1 = *(const ulonglong2*)(bb + k * 128 + 2);
                ulonglong2 y2 = *(const ulonglong2*)(bb + k * 128 + 4);
                ulonglong2 y3 = *(const ulonglong2*)(bb + k * 128 + 6);
                B[0]=y0.x; B[1]=y0.y; B[2]=y1.x; B[3]=y1.y;
                B[4]=y2.x; B[5]=y2.y; B[6]=y3.x; B[7]=y3.y;
            }
#pragma unroll
            for (int mi = 0; mi < 8; mi++)
#pragma unroll
                for (int n2 = 0; n2 < 8; n2++)
                    acc[mi][n2] = ffma2(A[mi], B[n2], acc[mi][n2]);
        }
        if (s + 1 < S) { STS_STAGE(cb ^ 1); }
        __syncthreads();
    }

    // epilogue: + bias, store
    u64 bv[8];
    const float* bp = bias + nB + tn * 16;
#pragma unroll
    for (int n2 = 0; n2 < 8; n2++) bv[n2] = *(const u64*)(bp + 2 * n2);
#pragma unroll
    for (int mi = 0; mi < 8; mi++) {
        u64* op = (u64*)(out + (size_t)(mB + tm * 8 + mi) * Gc + nB + tn * 16);
#pragma unroll
        for (int n2 = 0; n2 < 8; n2++) op[n2] = fadd2(acc[mi][n2], bv[n2]);
    }
#undef LDG_STAGE
#undef STS_STAGE
}

// ============================================================
// LSTM recurrence: 1 CTA per 2 batches (128 CTAs), 256 threads.
// Thread (j=tid>>1, g2=tid&1) owns gate rows {g2*256+j, g2*256+j+128}
// for BOTH batches, FFMA2 packed along k (natural h pairs, no dup).
// w_hh k-split: k<48 in smem (read once per CTA), k>=48 in registers.
// Gates finished in-thread -> shfl exchange -> 1 barrier/step.
// ============================================================
#define REC_SMEM (12*512*16 + 2*2*128*4 + 256*4)   // ws 96KB + hs ping-pong 2KB + red 1KB

__global__ __launch_bounds__(256, 1) void lstm_rec(
    const float* __restrict__ xg, const float* __restrict__ whh,
    const float* __restrict__ h0, float* __restrict__ hout,
    const float* __restrict__ fcw, const float* __restrict__ fcb,
    float* __restrict__ outp, int is_l0)
{
    extern __shared__ char smraw[];
    ulonglong2* ws = (ulonglong2*)smraw;               // [12 k4][512 rows]
    float* hs = (float*)(smraw + 12 * 512 * 16);       // [2 buf][2 batch][128]
    float* red = hs + 2 * 2 * 128;                     // [256]

    const int tid = threadIdx.x;
    const int j = tid >> 1, g2 = tid & 1;
    const int r0 = g2 * 256 + j, r1 = r0 + 128;
    const int b0 = blockIdx.x * 2;

    // smem weights: k in [0,48)
#pragma unroll
    for (int k4 = 0; k4 < 12; k4++) {
        ws[k4 * 512 + r0] = *(const ulonglong2*)&whh[(size_t)r0 * Hc + k4 * 4];
        ws[k4 * 512 + r1] = *(const ulonglong2*)&whh[(size_t)r1 * Hc + k4 * 4];
    }
    // register weights: k in [48,128), 20 k4-quads per row
    u64 w0r[40], w1r[40];
#pragma unroll
    for (int k4 = 0; k4 < 20; k4++) {
        ulonglong2 t0 = *(const ulonglong2*)&whh[(size_t)r0 * Hc + 48 + k4 * 4];
        w0r[2 * k4] = t0.x; w0r[2 * k4 + 1] = t0.y;
        ulonglong2 t1 = *(const ulonglong2*)&whh[(size_t)r1 * Hc + 48 + k4 * 4];
        w1r[2 * k4] = t1.x; w1r[2 * k4 + 1] = t1.y;
    }

    // init h (buffer 0), c = 0
    hs[g2 * 128 + j] = h0[(size_t)(b0 + g2) * Hc + j];
    float c = 0.f, hval = 0.f;

    const float* xA = xg + (size_t)b0 * Tc * Gc;
    const float* xB = xA + (size_t)Tc * Gc;
    float xA0 = __ldg(xA + r0), xA1 = __ldg(xA + r1);
    float xB0 = __ldg(xB + r0), xB1 = __ldg(xB + r1);
    __syncthreads();

#pragma unroll 1
    for (int t = 0; t < Tc; t++) {
        // prefetch next step's gate preactivations
        int tnx = (t + 1 < Tc) ? t + 1 : t;
        size_t off = (size_t)tnx * Gc;
        float nA0 = __ldg(xA + off + r0), nA1 = __ldg(xA + off + r1);
        float nB0 = __ldg(xB + off + r0), nB1 = __ldg(xB + off + r1);

        const float* hb = hs + (t & 1) * 256;
        u64 a00 = 0, a01 = 0, a10 = 0, a11 = 0;   // [row r0/r1][batch A/B]
#pragma unroll
        for (int k4 = 0; k4 < 12; k4++) {
            ulonglong2 w0 = ws[k4 * 512 + r0];
            ulonglong2 w1 = ws[k4 * 512 + r1];
            ulonglong2 hA = *(const ulonglong2*)(hb + k4 * 4);
            ulonglong2 hB = *(const ulonglong2*)(hb + 128 + k4 * 4);
            a00 = ffma2(w0.x, hA.x, a00); a00 = ffma2(w0.y, hA.y, a00);
            a01 = ffma2(w0.x, hB.x, a01); a01 = ffma2(w0.y, hB.y, a01);
            a10 = ffma2(w1.x, hA.x, a10); a10 = ffma2(w1.y, hA.y, a10);
            a11 = ffma2(w1.x, hB.x, a11); a11 = ffma2(w1.y, hB.y, a11);
        }
#pragma unroll
        for (int k4 = 0; k4 < 20; k4++) {
            ulonglong2 hA = *(const ulonglong2*)(hb + 48 + k4 * 4);
            ulonglong2 hB = *(const ulonglong2*)(hb + 128 + 48 + k4 * 4);
            a00 = ffma2(w0r[2*k4], hA.x, a00); a00 = ffma2(w0r[2*k4+1], hA.y, a00);
            a01 = ffma2(w0r[2*k4], hB.x, a01); a01 = ffma2(w0r[2*k4+1], hB.y, a01);
            a10 = ffma2(w1r[2*k4], hA.x, a10); a10 = ffma2(w1r[2*k4+1], hA.y, a10);
            a11 = ffma2(w1r[2*k4], hB.x, a11); a11 = ffma2(w1r[2*k4+1], hB.y, a11);
        }
        float v00 = red2(a00) + xA0;   // (r0, batch A)
        float v01 = red2(a01) + xB0;   // (r0, batch B)
        float v10 = red2(a10) + xA1;   // (r1, batch A)
        float v11 = red2(a11) + xB1;   // (r1, batch B)

        // exchange with partner lane (same j, other g2):
        // g2=0 keeps batch A (has i,f), g2=1 keeps batch B (has g,o)
        float s1 = g2 ? v00 : v01;                       // sends gA / iB
        float rc1 = __shfl_xor_sync(0xffffffffu, s1, 1); // recv gA / iB
        float s2 = g2 ? v10 : v11;                       // sends oA / fB
        float rc2 = __shfl_xor_sync(0xffffffffu, s2, 1); // recv oA / fB
        float gi, gf, gg, go;
        if (g2 == 0) { gi = v00; gf = v10; gg = rc1; go = rc2; }
        else         { gi = rc1; gf = rc2; gg = v01; go = v11; }

        float fI = sigf(gi), fF = sigf(gf), fG = tanh_f(gg), fO = sigf(go);
        c = fF * c + fI * fG;
        hval = fO * tanh_f(c);

        hs[((t + 1) & 1) * 256 + g2 * 128 + j] = hval;
        if (is_l0)
            hout[((size_t)(b0 + g2) * Tc + t) * Hc + j] = hval;

        xA0 = nA0; xA1 = nA1; xB0 = nB0; xB1 = nB1;
        __syncthreads();
    }

    if (!is_l0) {
        red[g2 * 128 + j] = hval * fcw[j];
        __syncthreads();
        if (tid < 2) {
            float s = fcb[0];
            for (int i = 0; i < 128; i++) s += red[tid * 128 + i];
            outp[b0 + tid] = s;
        }
    }
}

extern "C" void kernel_launch(void* const* d_in, const int* in_sizes, int n_in,
                              void* d_out, int out_size) {
    const float* x    = (const float*)d_in[0];
    const float* h0   = (const float*)d_in[1];
    const float* wih0 = (const float*)d_in[2];
    const float* whh0 = (const float*)d_in[3];
    const float* b0_  = (const float*)d_in[4];
    const float* wih1 = (const float*)d_in[5];
    const float* whh1 = (const float*)d_in[6];
    const float* b1_  = (const float*)d_in[7];
    const float* fcw  = (const float*)d_in[8];
    const float* fcb  = (const float*)d_in[9];
    float* out = (float*)d_out;

    cudaFuncSetAttribute(gemm_xw,  cudaFuncAttributeMaxDynamicSharedMemorySize, GEMM_SMEM);
    cudaFuncSetAttribute(lstm_rec, cudaFuncAttributeMaxDynamicSharedMemorySize, REC_SMEM);

    float *xgp, *h0sp;
    cudaGetSymbolAddress((void**)&xgp, g_xg);
    cudaGetSymbolAddress((void**)&h0sp, g_h0s);

    dim3 ggrid(Mc / 128, Gc / 256);
    // layer 0
    gemm_xw<<<ggrid, 256, GEMM_SMEM>>>(x, wih0, b0_, xgp, 64);
    lstm_rec<<<Bc / 2, 256, REC_SMEM>>>(xgp, whh0, h0, h0sp,
                                        nullptr, nullptr, nullptr, 1);
    // layer 1
    gemm_xw<<<ggrid, 256, GEMM_SMEM>>>(h0sp, wih1, b1_, xgp, 128);
    lstm_rec<<<Bc / 2, 256, REC_SMEM>>>(xgp, whh1, h0 + (size_t)Bc * Hc, nullptr,
                                        fcw, fcb, out, 0);
}

// round 7
// speedup vs baseline: 1.6609x; 1.6609x over previous
#include <cuda_runtime.h>

typedef unsigned long long u64;
typedef unsigned int u32;

#define Bc 256
#define Tc 1024
#define Hc 128
#define Gc 512
#define Mc (Bc*Tc)

// Scratch (device globals: sanctioned workaround for the no-alloc rule)
__device__ float g_xg[(size_t)Mc * Gc];   // [B*T, 512] gate preactivations
__device__ float g_h0s[(size_t)Mc * Hc];  // [B*T, 128] layer-0 hidden states

// ---------- packed f32x2 helpers ----------
static __device__ __forceinline__ u64 ffma2(u64 a, u64 b, u64 c) {
    u64 d; asm("fma.rn.f32x2 %0, %1, %2, %3;" : "=l"(d) : "l"(a), "l"(b), "l"(c)); return d;
}
static __device__ __forceinline__ u64 pack2(float lo, float hi) {
    u64 d; asm("mov.b64 %0, {%1, %2};" : "=l"(d) : "f"(lo), "f"(hi)); return d;
}
static __device__ __forceinline__ u64 dup2(float v) {
    u64 d; asm("mov.b64 %0, {%1, %1};" : "=l"(d) : "f"(v)); return d;
}
static __device__ __forceinline__ float lo_f(u64 v) {
    u32 a, b; asm("mov.b64 {%0, %1}, %2;" : "=r"(a), "=r"(b) : "l"(v));
    return __uint_as_float(a);
}
static __device__ __forceinline__ float hi_f(u64 v) {
    u32 a, b; asm("mov.b64 {%0, %1}, %2;" : "=r"(a), "=r"(b) : "l"(v));
    return __uint_as_float(b);
}
static __device__ __forceinline__ float red2(u64 v) {
    u32 a, b; asm("mov.b64 {%0, %1}, %2;" : "=r"(a), "=r"(b) : "l"(v));
    return __uint_as_float(a) + __uint_as_float(b);
}
static __device__ __forceinline__ float sigf(float x) {
    return __fdividef(1.f, 1.f + __expf(-x));
}
static __device__ __forceinline__ float tanh_f(float x) {
    return 1.f - __fdividef(2.f, 1.f + __expf(2.f * x));
}

// ============================================================
// GEMM (unchanged from the 6182us round, measured 1.27ms/launch):
// out[m][n] = sum_k X[m][k] * W[n][k] + bias[n]
// M=262144, N=512, K in {64,128}. BM=128, BN=64, BK=64.
// ============================================================
#define GEMM_SMEM (64*128*4 + 64*64*8)  // xs + wsd = 64KB

__global__ __launch_bounds__(256) void gemm_xw(
    const float* __restrict__ X, const float* __restrict__ W,
    const float* __restrict__ bias, float* __restrict__ out, int K)
{
    extern __shared__ float sm[];
    float* xs = sm;                        // [64][128] transposed x tile
    u64*   wsd = (u64*)(sm + 64 * 128);    // [64][64] dup'd W, permuted slots

    const int tid = threadIdx.x;
    const int tx = tid & 15;       // n dim (4 cols each)
    const int ty = tid >> 4;       // m dim (8 rows = 4 pairs each)
    const int mBase = blockIdx.x * 128;
    const int nBase = blockIdx.y * 64;

    u64 acc[4][4];
#pragma unroll
    for (int i = 0; i < 4; i++)
#pragma unroll
        for (int j = 0; j < 4; j++) acc[i][j] = 0ull;

    for (int s = 0; s < K; s += 64) {
#pragma unroll
        for (int i = 0; i < 8; i++) {
            int L = tid + 256 * i;
            int r = L >> 4;
            int q = L & 15;
            float4 v = *(const float4*)&X[(size_t)(mBase + r) * K + s + q * 4];
            xs[(q * 4 + 0) * 128 + r] = v.x;
            xs[(q * 4 + 1) * 128 + r] = v.y;
            xs[(q * 4 + 2) * 128 + r] = v.z;
            xs[(q * 4 + 3) * 128 + r] = v.w;
        }
#pragma unroll
        for (int i = 0; i < 4; i++) {
            int L = tid + 256 * i;
            int n = L >> 4;
            int q = L & 15;
            float4 v = *(const float4*)&W[(size_t)(nBase + n) * K + s + q * 4];
            int slot = ((n & 3) << 4) | (n >> 2);
            wsd[(q * 4 + 0) * 64 + slot] = dup2(v.x);
            wsd[(q * 4 + 1) * 64 + slot] = dup2(v.y);
            wsd[(q * 4 + 2) * 64 + slot] = dup2(v.z);
            wsd[(q * 4 + 3) * 64 + slot] = dup2(v.w);
        }
        __syncthreads();

#pragma unroll
        for (int k = 0; k < 64; k++) {
            u64 a0 = *(const u64*)&xs[k * 128 + ty * 8 + 0];
            u64 a1 = *(const u64*)&xs[k * 128 + ty * 8 + 2];
            u64 a2 = *(const u64*)&xs[k * 128 + ty * 8 + 4];
            u64 a3 = *(const u64*)&xs[k * 128 + ty * 8 + 6];
            u64 b0 = wsd[k * 64 + 0 * 16 + tx];
            u64 b1 = wsd[k * 64 + 1 * 16 + tx];
            u64 b2 = wsd[k * 64 + 2 * 16 + tx];
            u64 b3 = wsd[k * 64 + 3 * 16 + tx];
            acc[0][0] = ffma2(a0, b0, acc[0][0]);
            acc[0][1] = ffma2(a0, b1, acc[0][1]);
            acc[0][2] = ffma2(a0, b2, acc[0][2]);
            acc[0][3] = ffma2(a0, b3, acc[0][3]);
            acc[1][0] = ffma2(a1, b0, acc[1][0]);
            acc[1][1] = ffma2(a1, b1, acc[1][1]);
            acc[1][2] = ffma2(a1, b2, acc[1][2]);
            acc[1][3] = ffma2(a1, b3, acc[1][3]);
            acc[2][0] = ffma2(a2, b0, acc[2][0]);
            acc[2][1] = ffma2(a2, b1, acc[2][1]);
            acc[2][2] = ffma2(a2, b2, acc[2][2]);
            acc[2][3] = ffma2(a2, b3, acc[2][3]);
            acc[3][0] = ffma2(a3, b0, acc[3][0]);
            acc[3][1] = ffma2(a3, b1, acc[3][1]);
            acc[3][2] = ffma2(a3, b2, acc[3][2]);
            acc[3][3] = ffma2(a3, b3, acc[3][3]);
        }
        __syncthreads();
    }

    float4 bn = *(const float4*)&bias[nBase + tx * 4];
#pragma unroll
    for (int i = 0; i < 4; i++) {
        int m = mBase + ty * 8 + 2 * i;
        float4 lo, hi;
        lo.x = lo_f(acc[i][0]) + bn.x;
        lo.y = lo_f(acc[i][1]) + bn.y;
        lo.z = lo_f(acc[i][2]) + bn.z;
        lo.w = lo_f(acc[i][3]) + bn.w;
        hi.x = hi_f(acc[i][0]) + bn.x;
        hi.y = hi_f(acc[i][1]) + bn.y;
        hi.z = hi_f(acc[i][2]) + bn.z;
        hi.w = hi_f(acc[i][3]) + bn.w;
        *(float4*)&out[(size_t)m * Gc + nBase + tx * 4] = lo;
        *(float4*)&out[(size_t)(m + 1) * Gc + nBase + tx * 4] = hi;
    }
}

// ============================================================
// LSTM recurrence: 1 CTA per 2 batches (128 CTAs), 256 threads.
// Thread j owns gate rows {j, 256+j} for BOTH batches.
// FFMA2 packs k-parity: acc = (sum even k, sum odd k) -> w and h
// both load as natural float4 (no duplication, conflict-free).
// w_hh k-split: k<64 in smem (128KB, read once/step), k>=64 in regs.
// ============================================================
#define RSK 16   // smem k4-groups (k = 0..63)
#define RRK 16   // reg  k4-groups (k = 64..127)
#define REC_SMEM (RSK*512*16 + 2*2*128*4 + 2*512*4 + 256*4)  // 128K+2K+4K+1K

__global__ __launch_bounds__(256, 1) void lstm_rec(
    const float* __restrict__ xg, const float* __restrict__ whh,
    const float* __restrict__ h0, float* __restrict__ hout,
    const float* __restrict__ fcw, const float* __restrict__ fcb,
    float* __restrict__ outp, int is_l0)
{
    extern __shared__ char smraw[];
    ulonglong2* ws = (ulonglong2*)smraw;            // [RSK][512 rows] (4 k's each)
    float* hs  = (float*)(smraw + RSK * 512 * 16);  // [2 buf][2 batch][128]
    float* gb  = hs + 512;                          // [2 batch][512 rows]
    float* red = gb + 1024;                         // [256]

    const int tid = threadIdx.x;
    const int j = tid;              // rows j and 256+j
    const int b0 = blockIdx.x * 2;
    const int pb = tid >> 7, p = tid & 127;

    // smem weights: k in [0,64)
#pragma unroll
    for (int k4 = 0; k4 < RSK; k4++) {
        ws[k4 * 512 + j]       = *(const ulonglong2*)&whh[(size_t)j * Hc + k4 * 4];
        ws[k4 * 512 + 256 + j] = *(const ulonglong2*)&whh[(size_t)(256 + j) * Hc + k4 * 4];
    }
    // register weights: k in [64,128)
    u64 wr0[2 * RRK], wr1[2 * RRK];
#pragma unroll
    for (int k4 = 0; k4 < RRK; k4++) {
        ulonglong2 t0 = *(const ulonglong2*)&whh[(size_t)j * Hc + 64 + k4 * 4];
        wr0[2 * k4] = t0.x; wr0[2 * k4 + 1] = t0.y;
        ulonglong2 t1 = *(const ulonglong2*)&whh[(size_t)(256 + j) * Hc + 64 + k4 * 4];
        wr1[2 * k4] = t1.x; wr1[2 * k4 + 1] = t1.y;
    }

    // init h (buffer 0), c = 0
    hs[pb * 128 + p] = h0[(size_t)(b0 + pb) * Hc + p];
    float c = 0.f, hval = 0.f;

    const float* xA = xg + (size_t)b0 * Tc * Gc;
    const float* xB = xA + (size_t)Tc * Gc;
    float xa0 = __ldg(xA + j), xa1 = __ldg(xA + 256 + j);
    float xb0 = __ldg(xB + j), xb1 = __ldg(xB + 256 + j);
    __syncthreads();

#pragma unroll 1
    for (int t = 0; t < Tc; t++) {
        size_t off = (size_t)((t + 1 < Tc) ? t + 1 : t) * Gc;
        float na0 = __ldg(xA + off + j),       na1 = __ldg(xA + off + 256 + j);
        float nb0 = __ldg(xB + off + j),       nb1 = __ldg(xB + off + 256 + j);

        const float* hA = hs + (t & 1) * 256;
        const float* hB = hA + 128;
        u64 aA0 = 0, aB0 = 0, aA1 = 0, aB1 = 0;  // [row j / 256+j][batch A/B]
#pragma unroll
        for (int k4 = 0; k4 < RSK; k4++) {
            ulonglong2 w0 = ws[k4 * 512 + j];
            ulonglong2 w1 = ws[k4 * 512 + 256 + j];
            ulonglong2 ha = *(const ulonglong2*)(hA + k4 * 4);   // broadcast
            ulonglong2 hb = *(const ulonglong2*)(hB + k4 * 4);   // broadcast
            aA0 = ffma2(w0.x, ha.x, aA0); aA0 = ffma2(w0.y, ha.y, aA0);
            aB0 = ffma2(w0.x, hb.x, aB0); aB0 = ffma2(w0.y, hb.y, aB0);
            aA1 = ffma2(w1.x, ha.x, aA1); aA1 = ffma2(w1.y, ha.y, aA1);
            aB1 = ffma2(w1.x, hb.x, aB1); aB1 = ffma2(w1.y, hb.y, aB1);
        }
#pragma unroll
        for (int k4 = 0; k4 < RRK; k4++) {
            ulonglong2 ha = *(const ulonglong2*)(hA + 64 + k4 * 4);
            ulonglong2 hb = *(const ulonglong2*)(hB + 64 + k4 * 4);
            aA0 = ffma2(wr0[2*k4], ha.x, aA0); aA0 = ffma2(wr0[2*k4+1], ha.y, aA0);
            aB0 = ffma2(wr0[2*k4], hb.x, aB0); aB0 = ffma2(wr0[2*k4+1], hb.y, aB0);
            aA1 = ffma2(wr1[2*k4], ha.x, aA1); aA1 = ffma2(wr1[2*k4+1], ha.y, aA1);
            aB1 = ffma2(wr1[2*k4], hb.x, aB1); aB1 = ffma2(wr1[2*k4+1], hb.y, aB1);
        }
        gb[j]             = red2(aA0) + xa0;
        gb[256 + j]       = red2(aA1) + xa1;
        gb[512 + j]       = red2(aB0) + xb0;
        gb[512 + 256 + j] = red2(aB1) + xb1;
        __syncthreads();

        // pointwise: thread (pb, p)
        {
            float gi = gb[pb * 512 + p];
            float gf = gb[pb * 512 + 128 + p];
            float gg = gb[pb * 512 + 256 + p];
            float go = gb[pb * 512 + 384 + p];
            float fI = sigf(gi), fF = sigf(gf), fG = tanh_f(gg), fO = sigf(go);
            c = fF * c + fI * fG;
            hval = fO * tanh_f(c);
            hs[((t + 1) & 1) * 256 + pb * 128 + p] = hval;
            if (is_l0)
                hout[((size_t)(b0 + pb) * Tc + t) * Hc + p] = hval;
        }
        xa0 = na0; xa1 = na1; xb0 = nb0; xb1 = nb1;
        __syncthreads();
    }

    if (!is_l0) {
        red[pb * 128 + p] = hval * fcw[p];
        __syncthreads();
        if (tid < 2) {
            float s = fcb[0];
            for (int i = 0; i < 128; i++) s += red[tid * 128 + i];
            outp[b0 + tid] = s;
        }
    }
}

extern "C" void kernel_launch(void* const* d_in, const int* in_sizes, int n_in,
                              void* d_out, int out_size) {
    const float* x    = (const float*)d_in[0];
    const float* h0   = (const float*)d_in[1];
    const float* wih0 = (const float*)d_in[2];
    const float* whh0 = (const float*)d_in[3];
    const float* b0_  = (const float*)d_in[4];
    const float* wih1 = (const float*)d_in[5];
    const float* whh1 = (const float*)d_in[6];
    const float* b1_  = (const float*)d_in[7];
    const float* fcw  = (const float*)d_in[8];
    const float* fcb  = (const float*)d_in[9];
    float* out = (float*)d_out;

    cudaFuncSetAttribute(gemm_xw,  cudaFuncAttributeMaxDynamicSharedMemorySize, GEMM_SMEM);
    cudaFuncSetAttribute(lstm_rec, cudaFuncAttributeMaxDynamicSharedMemorySize, REC_SMEM);

    float *xgp, *h0sp;
    cudaGetSymbolAddress((void**)&xgp, g_xg);
    cudaGetSymbolAddress((void**)&h0sp, g_h0s);

    // layer 0
    gemm_xw<<<dim3(Mc / 128, Gc / 64), 256, GEMM_SMEM>>>(x, wih0, b0_, xgp, 64);
    lstm_rec<<<Bc / 2, 256, REC_SMEM>>>(xgp, whh0, h0, h0sp,
                                        nullptr, nullptr, nullptr, 1);
    // layer 1
    gemm_xw<<<dim3(Mc / 128, Gc / 64), 256, GEMM_SMEM>>>(h0sp, wih1, b1_, xgp, 128);
    lstm_rec<<<Bc / 2, 256, REC_SMEM>>>(xgp, whh1, h0 + (size_t)Bc * Hc, nullptr,
                                        fcw, fcb, out, 0);
}

// round 8
// speedup vs baseline: 2.0859x; 1.2559x over previous
#include <cuda_runtime.h>

typedef unsigned long long u64;
typedef unsigned int u32;

#define Bc 256
#define Tc 1024
#define Hc 128
#define Gc 512
#define Mc (Bc*Tc)

// Scratch (device globals: sanctioned workaround for the no-alloc rule)
__device__ float g_xg[(size_t)Mc * Gc];   // [B*T, 512] gate preactivations
__device__ float g_h0s[(size_t)Mc * Hc];  // [B*T, 128] layer-0 hidden states

// ---------- packed f32x2 helpers ----------
static __device__ __forceinline__ u64 ffma2(u64 a, u64 b, u64 c) {
    u64 d; asm("fma.rn.f32x2 %0, %1, %2, %3;" : "=l"(d) : "l"(a), "l"(b), "l"(c)); return d;
}
static __device__ __forceinline__ u64 pack2(float lo, float hi) {
    u64 d; asm("mov.b64 %0, {%1, %2};" : "=l"(d) : "f"(lo), "f"(hi)); return d;
}
static __device__ __forceinline__ float red2(u64 v) {
    u32 a, b; asm("mov.b64 {%0, %1}, %2;" : "=r"(a), "=r"(b) : "l"(v));
    return __uint_as_float(a) + __uint_as_float(b);
}
static __device__ __forceinline__ float sigf(float x) {
    return __fdividef(1.f, 1.f + __expf(-x));
}
static __device__ __forceinline__ float tanh_f(float x) {
    return 1.f - __fdividef(2.f, 1.f + __expf(2.f * x));
}

// ============================================================
// GEMM: out[m][n] = sum_k X[m][k]*W[n][k] + bias[n]
// M=262144, N=512, K in {64,128}. BM=128, BN=64, BK=32.
// k-parity FFMA2 packing, double-buffered smem, 256 thr, occ 2.
// Thread tile 8m x 4n (acc = 32 u64 = 64 regs).
// smem: A u64 [2][16 k2][129] (pad), B u64 [2][16 k2][64] (slot = ni*16+tn).
// ============================================================
#define AUS 129
#define GEMM_SMEM (2*16*AUS*8 + 2*16*64*8)   // 33024 + 16384 = 49408 B

__global__ __launch_bounds__(256, 2) void gemm_xw(
    const float* __restrict__ X, const float* __restrict__ W,
    const float* __restrict__ bias, float* __restrict__ out, int K)
{
    extern __shared__ u64 smg[];
    u64* aus = smg;                  // [2][16][129]
    u64* bsu = smg + 2 * 16 * AUS;   // [2][16][64]

    const int tid = threadIdx.x;
    const int tn = tid & 15, tm = tid >> 4;
    const int mB = blockIdx.x * 128, nB = blockIdx.y * 64;
    const int S = K >> 5;

    float4 aR[4], bR[2];

#define LDGS(s_) { \
    int kofs = (s_) * 32; \
    _Pragma("unroll") \
    for (int i = 0; i < 4; i++) { \
        int L = tid + 256 * i, r = L >> 3, q = L & 7; \
        aR[i] = *(const float4*)&X[(size_t)(mB + r) * K + kofs + q * 4]; \
    } \
    _Pragma("unroll") \
    for (int i = 0; i < 2; i++) { \
        int L = tid + 256 * i, n = L >> 3, q = L & 7; \
        bR[i] = *(const float4*)&W[(size_t)(nB + n) * K + kofs + q * 4]; \
    } \
}

#define STSS(buf) { \
    u64* au = aus + (buf) * 16 * AUS; \
    u64* bu = bsu + (buf) * 16 * 64; \
    _Pragma("unroll") \
    for (int i = 0; i < 4; i++) { \
        int L = tid + 256 * i, r = L >> 3, q = L & 7; \
        au[(2 * q) * AUS + r]     = pack2(aR[i].x, aR[i].y); \
        au[(2 * q + 1) * AUS + r] = pack2(aR[i].z, aR[i].w); \
    } \
    _Pragma("unroll") \
    for (int i = 0; i < 2; i++) { \
        int L = tid + 256 * i, n = L >> 3, q = L & 7; \
        int slot = (n & 3) * 16 + (n >> 2); \
        bu[(2 * q) * 64 + slot]     = pack2(bR[i].x, bR[i].y); \
        bu[(2 * q + 1) * 64 + slot] = pack2(bR[i].z, bR[i].w); \
    } \
}

    u64 acc[8][4];
#pragma unroll
    for (int mi = 0; mi < 8; mi++)
#pragma unroll
        for (int ni = 0; ni < 4; ni++) acc[mi][ni] = 0ull;

    LDGS(0);
    STSS(0);
    __syncthreads();

#pragma unroll 1
    for (int s = 0; s < S; s++) {
        int cb = s & 1;
        if (s + 1 < S) { LDGS(s + 1); }
        const u64* au = aus + cb * 16 * AUS + tm * 8;
        const u64* bu = bsu + cb * 16 * 64 + tn;
#pragma unroll
        for (int k2 = 0; k2 < 16; k2++) {
            u64 a[8], b[4];
#pragma unroll
            for (int mi = 0; mi < 8; mi++) a[mi] = au[k2 * AUS + mi];
#pragma unroll
            for (int ni = 0; ni < 4; ni++) b[ni] = bu[k2 * 64 + ni * 16];
#pragma unroll
            for (int mi = 0; mi < 8; mi++)
#pragma unroll
                for (int ni = 0; ni < 4; ni++)
                    acc[mi][ni] = ffma2(a[mi], b[ni], acc[mi][ni]);
        }
        if (s + 1 < S) { STSS(cb ^ 1); }
        __syncthreads();
    }

    float4 bn = *(const float4*)&bias[nB + tn * 4];
#pragma unroll
    for (int mi = 0; mi < 8; mi++) {
        float4 o;
        o.x = red2(acc[mi][0]) + bn.x;
        o.y = red2(acc[mi][1]) + bn.y;
        o.z = red2(acc[mi][2]) + bn.z;
        o.w = red2(acc[mi][3]) + bn.w;
        *(float4*)&out[(size_t)(mB + tm * 8 + mi) * Gc + nB + tn * 4] = o;
    }
#undef LDGS
#undef STSS
}

// ============================================================
// LSTM recurrence (unchanged from the 5509us round):
// 1 CTA per 2 batches (128 CTAs), 256 threads.
// Thread j owns gate rows {j, 256+j} for BOTH batches, k-parity FFMA2.
// w_hh k-split: k<64 in smem, k>=64 in regs.
// ============================================================
#define RSK 16   // smem k4-groups (k = 0..63)
#define RRK 16   // reg  k4-groups (k = 64..127)
#define REC_SMEM (RSK*512*16 + 2*2*128*4 + 2*512*4 + 256*4)  // 128K+2K+4K+1K

__global__ __launch_bounds__(256, 1) void lstm_rec(
    const float* __restrict__ xg, const float* __restrict__ whh,
    const float* __restrict__ h0, float* __restrict__ hout,
    const float* __restrict__ fcw, const float* __restrict__ fcb,
    float* __restrict__ outp, int is_l0)
{
    extern __shared__ char smraw[];
    ulonglong2* ws = (ulonglong2*)smraw;            // [RSK][512 rows]
    float* hs  = (float*)(smraw + RSK * 512 * 16);  // [2 buf][2 batch][128]
    float* gb  = hs + 512;                          // [2 batch][512 rows]
    float* red = gb + 1024;                         // [256]

    const int tid = threadIdx.x;
    const int j = tid;
    const int b0 = blockIdx.x * 2;
    const int pb = tid >> 7, p = tid & 127;

#pragma unroll
    for (int k4 = 0; k4 < RSK; k4++) {
        ws[k4 * 512 + j]       = *(const ulonglong2*)&whh[(size_t)j * Hc + k4 * 4];
        ws[k4 * 512 + 256 + j] = *(const ulonglong2*)&whh[(size_t)(256 + j) * Hc + k4 * 4];
    }
    u64 wr0[2 * RRK], wr1[2 * RRK];
#pragma unroll
    for (int k4 = 0; k4 < RRK; k4++) {
        ulonglong2 t0 = *(const ulonglong2*)&whh[(size_t)j * Hc + 64 + k4 * 4];
        wr0[2 * k4] = t0.x; wr0[2 * k4 + 1] = t0.y;
        ulonglong2 t1 = *(const ulonglong2*)&whh[(size_t)(256 + j) * Hc + 64 + k4 * 4];
        wr1[2 * k4] = t1.x; wr1[2 * k4 + 1] = t1.y;
    }

    hs[pb * 128 + p] = h0[(size_t)(b0 + pb) * Hc + p];
    float c = 0.f, hval = 0.f;

    const float* xA = xg + (size_t)b0 * Tc * Gc;
    const float* xB = xA + (size_t)Tc * Gc;
    float xa0 = __ldg(xA + j), xa1 = __ldg(xA + 256 + j);
    float xb0 = __ldg(xB + j), xb1 = __ldg(xB + 256 + j);
    __syncthreads();

#pragma unroll 1
    for (int t = 0; t < Tc; t++) {
        size_t off = (size_t)((t + 1 < Tc) ? t + 1 : t) * Gc;
        float na0 = __ldg(xA + off + j),       na1 = __ldg(xA + off + 256 + j);
        float nb0 = __ldg(xB + off + j),       nb1 = __ldg(xB + off + 256 + j);

        const float* hA = hs + (t & 1) * 256;
        const float* hB = hA + 128;
        u64 aA0 = 0, aB0 = 0, aA1 = 0, aB1 = 0;
#pragma unroll
        for (int k4 = 0; k4 < RSK; k4++) {
            ulonglong2 w0 = ws[k4 * 512 + j];
            ulonglong2 w1 = ws[k4 * 512 + 256 + j];
            ulonglong2 ha = *(const ulonglong2*)(hA + k4 * 4);
            ulonglong2 hb = *(const ulonglong2*)(hB + k4 * 4);
            aA0 = ffma2(w0.x, ha.x, aA0); aA0 = ffma2(w0.y, ha.y, aA0);
            aB0 = ffma2(w0.x, hb.x, aB0); aB0 = ffma2(w0.y, hb.y, aB0);
            aA1 = ffma2(w1.x, ha.x, aA1); aA1 = ffma2(w1.y, ha.y, aA1);
            aB1 = ffma2(w1.x, hb.x, aB1); aB1 = ffma2(w1.y, hb.y, aB1);
        }
#pragma unroll
        for (int k4 = 0; k4 < RRK; k4++) {
            ulonglong2 ha = *(const ulonglong2*)(hA + 64 + k4 * 4);
            ulonglong2 hb = *(const ulonglong2*)(hB + 64 + k4 * 4);
            aA0 = ffma2(wr0[2*k4], ha.x, aA0); aA0 = ffma2(wr0[2*k4+1], ha.y, aA0);
            aB0 = ffma2(wr0[2*k4], hb.x, aB0); aB0 = ffma2(wr0[2*k4+1], hb.y, aB0);
            aA1 = ffma2(wr1[2*k4], ha.x, aA1); aA1 = ffma2(wr1[2*k4+1], ha.y, aA1);
            aB1 = ffma2(wr1[2*k4], hb.x, aB1); aB1 = ffma2(wr1[2*k4+1], hb.y, aB1);
        }
        gb[j]             = red2(aA0) + xa0;
        gb[256 + j]       = red2(aA1) + xa1;
        gb[512 + j]       = red2(aB0) + xb0;
        gb[512 + 256 + j] = red2(aB1) + xb1;
        __syncthreads();

        {
            float gi = gb[pb * 512 + p];
            float gf = gb[pb * 512 + 128 + p];
            float gg = gb[pb * 512 + 256 + p];
            float go = gb[pb * 512 + 384 + p];
            float fI = sigf(gi), fF = sigf(gf), fG = tanh_f(gg), fO = sigf(go);
            c = fF * c + fI * fG;
            hval = fO * tanh_f(c);
            hs[((t + 1) & 1) * 256 + pb * 128 + p] = hval;
            if (is_l0)
                hout[((size_t)(b0 + pb) * Tc + t) * Hc + p] = hval;
        }
        xa0 = na0; xa1 = na1; xb0 = nb0; xb1 = nb1;
        __syncthreads();
    }

    if (!is_l0) {
        red[pb * 128 + p] = hval * fcw[p];
        __syncthreads();
        if (tid < 2) {
            float s = fcb[0];
            for (int i = 0; i < 128; i++) s += red[tid * 128 + i];
            outp[b0 + tid] = s;
        }
    }
}

extern "C" void kernel_launch(void* const* d_in, const int* in_sizes, int n_in,
                              void* d_out, int out_size) {
    const float* x    = (const float*)d_in[0];
    const float* h0   = (const float*)d_in[1];
    const float* wih0 = (const float*)d_in[2];
    const float* whh0 = (const float*)d_in[3];
    const float* b0_  = (const float*)d_in[4];
    const float* wih1 = (const float*)d_in[5];
    const float* whh1 = (const float*)d_in[6];
    const float* b1_  = (const float*)d_in[7];
    const float* fcw  = (const float*)d_in[8];
    const float* fcb  = (const float*)d_in[9];
    float* out = (float*)d_out;

    cudaFuncSetAttribute(gemm_xw,  cudaFuncAttributeMaxDynamicSharedMemorySize, GEMM_SMEM);
    cudaFuncSetAttribute(lstm_rec, cudaFuncAttributeMaxDynamicSharedMemorySize, REC_SMEM);

    float *xgp, *h0sp;
    cudaGetSymbolAddress((void**)&xgp, g_xg);
    cudaGetSymbolAddress((void**)&h0sp, g_h0s);

    dim3 ggrid(Mc / 128, Gc / 64);
    // layer 0
    gemm_xw<<<ggrid, 256, GEMM_SMEM>>>(x, wih0, b0_, xgp, 64);
    lstm_rec<<<Bc / 2, 256, REC_SMEM>>>(xgp, whh0, h0, h0sp,
                                        nullptr, nullptr, nullptr, 1);
    // layer 1
    gemm_xw<<<ggrid, 256, GEMM_SMEM>>>(h0sp, wih1, b1_, xgp, 128);
    lstm_rec<<<Bc / 2, 256, REC_SMEM>>>(xgp, whh1, h0 + (size_t)Bc * Hc, nullptr,
                                        fcw, fcb, out, 0);
}

// round 11
// speedup vs baseline: 2.6149x; 1.2536x over previous
#include <cuda_runtime.h>
#include <cuda_bf16.h>

typedef unsigned long long u64;
typedef unsigned int u32;

#define Bc 256
#define Tc 1024
#define Hc 128
#define Gc 512
#define Mc (Bc*Tc)

// Scratch (device globals: sanctioned workaround for the no-alloc rule)
__device__ float g_xg[(size_t)Mc * Gc];    // [B*T, 512] gate preactivations
__device__ float g_h0s[(size_t)Mc * Hc];   // [B*T, 128] layer-0 hidden states
__device__ __nv_bfloat16 g_whi0[Gc * 64];  // w_ih_0 bf16 hi
__device__ __nv_bfloat16 g_wlo0[Gc * 64];  // w_ih_0 bf16 lo
__device__ __nv_bfloat16 g_whi1[Gc * Hc];  // w_ih_1 bf16 hi
__device__ __nv_bfloat16 g_wlo1[Gc * Hc];  // w_ih_1 bf16 lo

// ---------- packed f32x2 helpers (recurrence) ----------
static __device__ __forceinline__ u64 ffma2(u64 a, u64 b, u64 c) {
    u64 d; asm("fma.rn.f32x2 %0, %1, %2, %3;" : "=l"(d) : "l"(a), "l"(b), "l"(c)); return d;
}
static __device__ __forceinline__ float red2(u64 v) {
    u32 a, b; asm("mov.b64 {%0, %1}, %2;" : "=r"(a), "=r"(b) : "l"(v));
    return __uint_as_float(a) + __uint_as_float(b);
}
static __device__ __forceinline__ float sigf(float x) {
    return __fdividef(1.f, 1.f + __expf(-x));
}
static __device__ __forceinline__ float tanh_f(float x) {
    return 1.f - __fdividef(2.f, 1.f + __expf(2.f * x));
}

// ---------- mma.sync helpers (baseline PTX, sm_80+: compiles for sm_103) ----------
static __device__ __forceinline__ u32 smem_u32(const void* p) {
    u32 a;
    asm("{ .reg .u64 t; cvta.to.shared.u64 t, %1; cvt.u32.u64 %0, t; }"
        : "=r"(a) : "l"(p));
    return a;
}
static __device__ __forceinline__ void ldm_x4(u32* r, u32 a) {
    asm volatile("ldmatrix.sync.aligned.m8n8.x4.shared.b16 {%0,%1,%2,%3}, [%4];"
        : "=r"(r[0]), "=r"(r[1]), "=r"(r[2]), "=r"(r[3]) : "r"(a));
}
static __device__ __forceinline__ void mma16816(float* d, const u32* a, const u32* b) {
    asm volatile(
        "mma.sync.aligned.m16n8k16.row.col.f32.bf16.bf16.f32 "
        "{%0,%1,%2,%3}, {%4,%5,%6,%7}, {%8,%9}, {%0,%1,%2,%3};"
        : "+f"(d[0]), "+f"(d[1]), "+f"(d[2]), "+f"(d[3])
        : "r"(a[0]), "r"(a[1]), "r"(a[2]), "r"(a[3]), "r"(b[0]), "r"(b[1]));
}
static __device__ __forceinline__ u32 pbf2(float lo, float hi) {
    __nv_bfloat162 t = __floats2bfloat162_rn(lo, hi);
    return *(u32*)&t;
}

// ============================================================
// W pre-convert: f32 -> bf16 hi + bf16 lo (residual)
// ============================================================
__global__ void conv_w(const float* __restrict__ src,
                       __nv_bfloat16* __restrict__ hi,
                       __nv_bfloat16* __restrict__ lo, int n)
{
    int i = blockIdx.x * 256 + threadIdx.x;
    if (i < n) {
        float v = src[i];
        __nv_bfloat16 h = __float2bfloat16_rn(v);
        hi[i] = h;
        lo[i] = __float2bfloat16_rn(v - __bfloat162float(h));
    }
}

// ============================================================
// GEMM via mma.sync bf16x3: out[m][n] = sum_k X[m][k]*W[n][k] + bias[n]
// BM=128, BN=128 (grid.y=4), K chunked by 64. 256 thr, 8 warps (32m x 64n).
// smem per chunk: Ahi/Alo/Bhi/Blo each [128 rows][64 bf16] = 16KB -> 64KB.
// 16B-chunk XOR swizzle: chunk' = chunk ^ (row & 7).
// Products: AhiBhi + AloBhi + AhiBlo accumulated in f32.
// ============================================================
#define GT_SMEM 65536

__global__ __launch_bounds__(256, 2) void gemm_mma(
    const float* __restrict__ X,
    const __nv_bfloat16* __restrict__ Whi,
    const __nv_bfloat16* __restrict__ Wlo,
    const float* __restrict__ bias,
    float* __restrict__ out, int K)
{
    extern __shared__ char sm[];
    const int tid = threadIdx.x, lane = tid & 31, wid = tid >> 5;
    const int mB = blockIdx.x * 128, nB = blockIdx.y * 128;
    const u32 smb = smem_u32(sm);
    const u32 AHI = 0, ALO = 16384, BHI = 32768, BLO = 49152;

    const int wm = wid & 3, wn = wid >> 2;
    const int m0w = wm * 32, n0w = wn * 64;

    float acc[2][8][4];
#pragma unroll
    for (int mt = 0; mt < 2; mt++)
#pragma unroll
        for (int nt = 0; nt < 8; nt++)
#pragma unroll
            for (int i = 0; i < 4; i++) acc[mt][nt][i] = 0.f;

#pragma unroll 1
    for (int kc = 0; kc < K; kc += 64) {
        if (kc) __syncthreads();
        // ---- stage A: load X f32, split hi/lo, store swizzled bf16 ----
#pragma unroll
        for (int i = 0; i < 4; i++) {
            int g = tid + 256 * i;
            int row = g >> 3, grp = g & 7;
            const float* xp = X + (size_t)(mB + row) * K + kc + grp * 8;
            float4 v0 = *(const float4*)xp;
            float4 v1 = *(const float4*)(xp + 4);
            __nv_bfloat16 h0 = __float2bfloat16_rn(v0.x), h1 = __float2bfloat16_rn(v0.y);
            __nv_bfloat16 h2 = __float2bfloat16_rn(v0.z), h3 = __float2bfloat16_rn(v0.w);
            __nv_bfloat16 h4 = __float2bfloat16_rn(v1.x), h5 = __float2bfloat16_rn(v1.y);
            __nv_bfloat16 h6 = __float2bfloat16_rn(v1.z), h7 = __float2bfloat16_rn(v1.w);
            uint4 hq, lq;
            hq.x = (u32)__bfloat16_as_ushort(h0) | ((u32)__bfloat16_as_ushort(h1) << 16);
            hq.y = (u32)__bfloat16_as_ushort(h2) | ((u32)__bfloat16_as_ushort(h3) << 16);
            hq.z = (u32)__bfloat16_as_ushort(h4) | ((u32)__bfloat16_as_ushort(h5) << 16);
            hq.w = (u32)__bfloat16_as_ushort(h6) | ((u32)__bfloat16_as_ushort(h7) << 16);
            lq.x = pbf2(v0.x - __bfloat162float(h0), v0.y - __bfloat162float(h1));
            lq.y = pbf2(v0.z - __bfloat162float(h2), v0.w - __bfloat162float(h3));
            lq.z = pbf2(v1.x - __bfloat162float(h4), v1.y - __bfloat162float(h5));
            lq.w = pbf2(v1.z - __bfloat162float(h6), v1.w - __bfloat162float(h7));
            u32 off = (u32)(row * 128 + ((grp ^ (row & 7)) << 4));
            *(uint4*)(sm + AHI + off) = hq;
            *(uint4*)(sm + ALO + off) = lq;
        }
        // ---- stage B: W bf16 hi/lo pre-converted ----
#pragma unroll
        for (int i = 0; i < 4; i++) {
            int g = tid + 256 * i;
            int row = g >> 3, grp = g & 7;
            size_t gix = (size_t)(nB + row) * K + kc + grp * 8;
            uint4 hv = *(const uint4*)(Whi + gix);
            uint4 lv = *(const uint4*)(Wlo + gix);
            u32 off = (u32)(row * 128 + ((grp ^ (row & 7)) << 4));
            *(uint4*)(sm + BHI + off) = hv;
            *(uint4*)(sm + BLO + off) = lv;
        }
        __syncthreads();

        // ---- 4 k16 steps per chunk ----
#pragma unroll
        for (int kt = 0; kt < 4; kt++) {
            u32 ah[2][4], al[2][4], bb[4][4];
            // A fragments (hi + lo)
#pragma unroll
            for (int mt = 0; mt < 2; mt++) {
                int sub = lane >> 3;
                int mrow = m0w + mt * 16 + (sub & 1) * 8 + (lane & 7);
                int c = kt * 2 + (sub >> 1);
                u32 ad = smb + mrow * 128 + ((u32)(c ^ (mrow & 7)) << 4);
                ldm_x4(ah[mt], ad + AHI);
                ldm_x4(al[mt], ad + ALO);
            }
            // B hi fragments: 4 x4 loads cover 8 n-tiles
            int subb = lane >> 3;
            u32 bad[4];
#pragma unroll
            for (int np = 0; np < 4; np++) {
                int nrow = n0w + np * 16 + (subb >> 1) * 8 + (lane & 7);
                int c = kt * 2 + (subb & 1);
                bad[np] = smb + nrow * 128 + ((u32)(c ^ (nrow & 7)) << 4);
                ldm_x4(bb[np], bad[np] + BHI);
            }
#pragma unroll
            for (int mt = 0; mt < 2; mt++)
#pragma unroll
                for (int nt = 0; nt < 8; nt++)
                    mma16816(acc[mt][nt], ah[mt], &bb[nt >> 1][(nt & 1) * 2]);
#pragma unroll
            for (int mt = 0; mt < 2; mt++)
#pragma unroll
                for (int nt = 0; nt < 8; nt++)
                    mma16816(acc[mt][nt], al[mt], &bb[nt >> 1][(nt & 1) * 2]);
            // B lo fragments (overwrite bb), then Ahi * Blo
#pragma unroll
            for (int np = 0; np < 4; np++)
                ldm_x4(bb[np], bad[np] + BLO);
#pragma unroll
            for (int mt = 0; mt < 2; mt++)
#pragma unroll
                for (int nt = 0; nt < 8; nt++)
                    mma16816(acc[mt][nt], ah[mt], &bb[nt >> 1][(nt & 1) * 2]);
        }
    }

    // ---- epilogue: + bias, store f32 ----
#pragma unroll
    for (int mt = 0; mt < 2; mt++)
#pragma unroll
        for (int nt = 0; nt < 8; nt++) {
            int m = mB + m0w + mt * 16 + (lane >> 2);
            int n = nB + n0w + nt * 8 + (lane & 3) * 2;
            float2 bv = *(const float2*)&bias[n];
            float2 o0, o1;
            o0.x = acc[mt][nt][0] + bv.x;
            o0.y = acc[mt][nt][1] + bv.y;
            o1.x = acc[mt][nt][2] + bv.x;
            o1.y = acc[mt][nt][3] + bv.y;
            *(float2*)&out[(size_t)m * Gc + n] = o0;
            *(float2*)&out[(size_t)(m + 8) * Gc + n] = o1;
        }
}

// ============================================================
// LSTM recurrence (unchanged from the 4387us round)
// ============================================================
#define RSK 16
#define RRK 16
#define REC_SMEM (RSK*512*16 + 2*2*128*4 + 2*512*4 + 256*4)

__global__ __launch_bounds__(256, 1) void lstm_rec(
    const float* __restrict__ xg, const float* __restrict__ whh,
    const float* __restrict__ h0, float* __restrict__ hout,
    const float* __restrict__ fcw, const float* __restrict__ fcb,
    float* __restrict__ outp, int is_l0)
{
    extern __shared__ char smraw[];
    ulonglong2* ws = (ulonglong2*)smraw;
    float* hs  = (float*)(smraw + RSK * 512 * 16);
    float* gb  = hs + 512;
    float* red = gb + 1024;

    const int tid = threadIdx.x;
    const int j = tid;
    const int b0 = blockIdx.x * 2;
    const int pb = tid >> 7, p = tid & 127;

#pragma unroll
    for (int k4 = 0; k4 < RSK; k4++) {
        ws[k4 * 512 + j]       = *(const ulonglong2*)&whh[(size_t)j * Hc + k4 * 4];
        ws[k4 * 512 + 256 + j] = *(const ulonglong2*)&whh[(size_t)(256 + j) * Hc + k4 * 4];
    }
    u64 wr0[2 * RRK], wr1[2 * RRK];
#pragma unroll
    for (int k4 = 0; k4 < RRK; k4++) {
        ulonglong2 t0 = *(const ulonglong2*)&whh[(size_t)j * Hc + 64 + k4 * 4];
        wr0[2 * k4] = t0.x; wr0[2 * k4 + 1] = t0.y;
        ulonglong2 t1 = *(const ulonglong2*)&whh[(size_t)(256 + j) * Hc + 64 + k4 * 4];
        wr1[2 * k4] = t1.x; wr1[2 * k4 + 1] = t1.y;
    }

    hs[pb * 128 + p] = h0[(size_t)(b0 + pb) * Hc + p];
    float c = 0.f, hval = 0.f;

    const float* xA = xg + (size_t)b0 * Tc * Gc;
    const float* xB = xA + (size_t)Tc * Gc;
    float xa0 = __ldg(xA + j), xa1 = __ldg(xA + 256 + j);
    float xb0 = __ldg(xB + j), xb1 = __ldg(xB + 256 + j);
    __syncthreads();

#pragma unroll 1
    for (int t = 0; t < Tc; t++) {
        size_t off = (size_t)((t + 1 < Tc) ? t + 1 : t) * Gc;
        float na0 = __ldg(xA + off + j),       na1 = __ldg(xA + off + 256 + j);
        float nb0 = __ldg(xB + off + j),       nb1 = __ldg(xB + off + 256 + j);

        const float* hA = hs + (t & 1) * 256;
        const float* hB = hA + 128;
        u64 aA0 = 0, aB0 = 0, aA1 = 0, aB1 = 0;
#pragma unroll
        for (int k4 = 0; k4 < RSK; k4++) {
            ulonglong2 w0 = ws[k4 * 512 + j];
            ulonglong2 w1 = ws[k4 * 512 + 256 + j];
            ulonglong2 ha = *(const ulonglong2*)(hA + k4 * 4);
            ulonglong2 hb = *(const ulonglong2*)(hB + k4 * 4);
            aA0 = ffma2(w0.x, ha.x, aA0); aA0 = ffma2(w0.y, ha.y, aA0);
            aB0 = ffma2(w0.x, hb.x, aB0); aB0 = ffma2(w0.y, hb.y, aB0);
            aA1 = ffma2(w1.x, ha.x, aA1); aA1 = ffma2(w1.y, ha.y, aA1);
            aB1 = ffma2(w1.x, hb.x, aB1); aB1 = ffma2(w1.y, hb.y, aB1);
        }
#pragma unroll
        for (int k4 = 0; k4 < RRK; k4++) {
            ulonglong2 ha = *(const ulonglong2*)(hA + 64 + k4 * 4);
            ulonglong2 hb = *(const ulonglong2*)(hB + 64 + k4 * 4);
            aA0 = ffma2(wr0[2*k4], ha.x, aA0); aA0 = ffma2(wr0[2*k4+1], ha.y, aA0);
            aB0 = ffma2(wr0[2*k4], hb.x, aB0); aB0 = ffma2(wr0[2*k4+1], hb.y, aB0);
            aA1 = ffma2(wr1[2*k4], ha.x, aA1); aA1 = ffma2(wr1[2*k4+1], ha.y, aA1);
            aB1 = ffma2(wr1[2*k4], hb.x, aB1); aB1 = ffma2(wr1[2*k4+1], hb.y, aB1);
        }
        gb[j]             = red2(aA0) + xa0;
        gb[256 + j]       = red2(aA1) + xa1;
        gb[512 + j]       = red2(aB0) + xb0;
        gb[512 + 256 + j] = red2(aB1) + xb1;
        __syncthreads();

        {
            float gi = gb[pb * 512 + p];
            float gf = gb[pb * 512 + 128 + p];
            float gg = gb[pb * 512 + 256 + p];
            float go = gb[pb * 512 + 384 + p];
            float fI = sigf(gi), fF = sigf(gf), fG = tanh_f(gg), fO = sigf(go);
            c = fF * c + fI * fG;
            hval = fO * tanh_f(c);
            hs[((t + 1) & 1) * 256 + pb * 128 + p] = hval;
            if (is_l0)
                hout[((size_t)(b0 + pb) * Tc + t) * Hc + p] = hval;
        }
        xa0 = na0; xa1 = na1; xb0 = nb0; xb1 = nb1;
        __syncthreads();
    }

    if (!is_l0) {
        red[pb * 128 + p] = hval * fcw[p];
        __syncthreads();
        if (tid < 2) {
            float s = fcb[0];
            for (int i = 0; i < 128; i++) s += red[tid * 128 + i];
            outp[b0 + tid] = s;
        }
    }
}

extern "C" void kernel_launch(void* const* d_in, const int* in_sizes, int n_in,
                              void* d_out, int out_size) {
    const float* x    = (const float*)d_in[0];
    const float* h0   = (const float*)d_in[1];
    const float* wih0 = (const float*)d_in[2];
    const float* whh0 = (const float*)d_in[3];
    const float* b0_  = (const float*)d_in[4];
    const float* wih1 = (const float*)d_in[5];
    const float* whh1 = (const float*)d_in[6];
    const float* b1_  = (const float*)d_in[7];
    const float* fcw  = (const float*)d_in[8];
    const float* fcb  = (const float*)d_in[9];
    float* out = (float*)d_out;

    cudaFuncSetAttribute(gemm_mma, cudaFuncAttributeMaxDynamicSharedMemorySize, GT_SMEM);
    cudaFuncSetAttribute(lstm_rec, cudaFuncAttributeMaxDynamicSharedMemorySize, REC_SMEM);

    float *xgp, *h0sp;
    cudaGetSymbolAddress((void**)&xgp, g_xg);
    cudaGetSymbolAddress((void**)&h0sp, g_h0s);
    __nv_bfloat16 *whi0, *wlo0, *whi1, *wlo1;
    cudaGetSymbolAddress((void**)&whi0, g_whi0);
    cudaGetSymbolAddress((void**)&wlo0, g_wlo0);
    cudaGetSymbolAddress((void**)&whi1, g_whi1);
    cudaGetSymbolAddress((void**)&wlo1, g_wlo1);

    // pre-convert input-GEMM weights to bf16 hi/lo
    conv_w<<<(Gc * 64 + 255) / 256, 256>>>(wih0, whi0, wlo0, Gc * 64);
    conv_w<<<(Gc * Hc + 255) / 256, 256>>>(wih1, whi1, wlo1, Gc * Hc);

    dim3 ggrid(Mc / 128, Gc / 128);
    // layer 0 (K=64)
    gemm_mma<<<ggrid, 256, GT_SMEM>>>(x, whi0, wlo0, b0_, xgp, 64);
    lstm_rec<<<Bc / 2, 256, REC_SMEM>>>(xgp, whh0, h0, h0sp,
                                        nullptr, nullptr, nullptr, 1);
    // layer 1 (K=128)
    gemm_mma<<<ggrid, 256, GT_SMEM>>>(h0sp, whi1, wlo1, b1_, xgp, 128);
    lstm_rec<<<Bc / 2, 256, REC_SMEM>>>(xgp, whh1, h0 + (size_t)Bc * Hc, nullptr,
                                        fcw, fcb, out, 0);
}

// round 12
// speedup vs baseline: 2.7643x; 1.0571x over previous
#include <cuda_runtime.h>
#include <cuda_bf16.h>

typedef unsigned long long u64;
typedef unsigned int u32;

#define Bc 256
#define Tc 1024
#define Hc 128
#define Gc 512
#define Mc (Bc*Tc)

// Scratch (device globals: sanctioned workaround for the no-alloc rule)
__device__ float g_xg[(size_t)Mc * Gc];    // [B*T, 512] gate preactivations
__device__ float g_h0s[(size_t)Mc * Hc];   // [B*T, 128] layer-0 hidden states
__device__ __nv_bfloat16 g_whi0[Gc * 64];  // w_ih_0 bf16 hi
__device__ __nv_bfloat16 g_wlo0[Gc * 64];  // w_ih_0 bf16 lo
__device__ __nv_bfloat16 g_whi1[Gc * Hc];  // w_ih_1 bf16 hi
__device__ __nv_bfloat16 g_wlo1[Gc * Hc];  // w_ih_1 bf16 lo

// ---------- packed f32x2 helpers (recurrence) ----------
static __device__ __forceinline__ u64 ffma2(u64 a, u64 b, u64 c) {
    u64 d; asm("fma.rn.f32x2 %0, %1, %2, %3;" : "=l"(d) : "l"(a), "l"(b), "l"(c)); return d;
}
static __device__ __forceinline__ float red2(u64 v) {
    u32 a, b; asm("mov.b64 {%0, %1}, %2;" : "=r"(a), "=r"(b) : "l"(v));
    return __uint_as_float(a) + __uint_as_float(b);
}
static __device__ __forceinline__ float sigf(float x) {
    return __fdividef(1.f, 1.f + __expf(-x));
}
static __device__ __forceinline__ float tanh_f(float x) {
    return 1.f - __fdividef(2.f, 1.f + __expf(2.f * x));
}

// ---------- mma.sync helpers (baseline PTX, sm_80+: compiles for sm_103) ----------
static __device__ __forceinline__ u32 smem_u32(const void* p) {
    u32 a;
    asm("{ .reg .u64 t; cvta.to.shared.u64 t, %1; cvt.u32.u64 %0, t; }"
        : "=r"(a) : "l"(p));
    return a;
}
static __device__ __forceinline__ void ldm_x4(u32* r, u32 a) {
    asm volatile("ldmatrix.sync.aligned.m8n8.x4.shared.b16 {%0,%1,%2,%3}, [%4];"
        : "=r"(r[0]), "=r"(r[1]), "=r"(r[2]), "=r"(r[3]) : "r"(a));
}
static __device__ __forceinline__ void mma16816(float* d, const u32* a, const u32* b) {
    asm volatile(
        "mma.sync.aligned.m16n8k16.row.col.f32.bf16.bf16.f32 "
        "{%0,%1,%2,%3}, {%4,%5,%6,%7}, {%8,%9}, {%0,%1,%2,%3};"
        : "+f"(d[0]), "+f"(d[1]), "+f"(d[2]), "+f"(d[3])
        : "r"(a[0]), "r"(a[1]), "r"(a[2]), "r"(a[3]), "r"(b[0]), "r"(b[1]));
}
static __device__ __forceinline__ u32 pbf2(float lo, float hi) {
    __nv_bfloat162 t = __floats2bfloat162_rn(lo, hi);
    return *(u32*)&t;
}

// ============================================================
// W pre-convert: f32 -> bf16 hi + bf16 lo (residual)
// ============================================================
__global__ void conv_w(const float* __restrict__ src,
                       __nv_bfloat16* __restrict__ hi,
                       __nv_bfloat16* __restrict__ lo, int n)
{
    int i = blockIdx.x * 256 + threadIdx.x;
    if (i < n) {
        float v = src[i];
        __nv_bfloat16 h = __float2bfloat16_rn(v);
        hi[i] = h;
        lo[i] = __float2bfloat16_rn(v - __bfloat162float(h));
    }
}

// ============================================================
// GEMM via mma.sync bf16x3 (unchanged from the 3499us round)
// ============================================================
#define GT_SMEM 65536

__global__ __launch_bounds__(256, 2) void gemm_mma(
    const float* __restrict__ X,
    const __nv_bfloat16* __restrict__ Whi,
    const __nv_bfloat16* __restrict__ Wlo,
    const float* __restrict__ bias,
    float* __restrict__ out, int K)
{
    extern __shared__ char sm[];
    const int tid = threadIdx.x, lane = tid & 31, wid = tid >> 5;
    const int mB = blockIdx.x * 128, nB = blockIdx.y * 128;
    const u32 smb = smem_u32(sm);
    const u32 AHI = 0, ALO = 16384, BHI = 32768, BLO = 49152;

    const int wm = wid & 3, wn = wid >> 2;
    const int m0w = wm * 32, n0w = wn * 64;

    float acc[2][8][4];
#pragma unroll
    for (int mt = 0; mt < 2; mt++)
#pragma unroll
        for (int nt = 0; nt < 8; nt++)
#pragma unroll
            for (int i = 0; i < 4; i++) acc[mt][nt][i] = 0.f;

#pragma unroll 1
    for (int kc = 0; kc < K; kc += 64) {
        if (kc) __syncthreads();
#pragma unroll
        for (int i = 0; i < 4; i++) {
            int g = tid + 256 * i;
            int row = g >> 3, grp = g & 7;
            const float* xp = X + (size_t)(mB + row) * K + kc + grp * 8;
            float4 v0 = *(const float4*)xp;
            float4 v1 = *(const float4*)(xp + 4);
            __nv_bfloat16 h0 = __float2bfloat16_rn(v0.x), h1 = __float2bfloat16_rn(v0.y);
            __nv_bfloat16 h2 = __float2bfloat16_rn(v0.z), h3 = __float2bfloat16_rn(v0.w);
            __nv_bfloat16 h4 = __float2bfloat16_rn(v1.x), h5 = __float2bfloat16_rn(v1.y);
            __nv_bfloat16 h6 = __float2bfloat16_rn(v1.z), h7 = __float2bfloat16_rn(v1.w);
            uint4 hq, lq;
            hq.x = (u32)__bfloat16_as_ushort(h0) | ((u32)__bfloat16_as_ushort(h1) << 16);
            hq.y = (u32)__bfloat16_as_ushort(h2) | ((u32)__bfloat16_as_ushort(h3) << 16);
            hq.z = (u32)__bfloat16_as_ushort(h4) | ((u32)__bfloat16_as_ushort(h5) << 16);
            hq.w = (u32)__bfloat16_as_ushort(h6) | ((u32)__bfloat16_as_ushort(h7) << 16);
            lq.x = pbf2(v0.x - __bfloat162float(h0), v0.y - __bfloat162float(h1));
            lq.y = pbf2(v0.z - __bfloat162float(h2), v0.w - __bfloat162float(h3));
            lq.z = pbf2(v1.x - __bfloat162float(h4), v1.y - __bfloat162float(h5));
            lq.w = pbf2(v1.z - __bfloat162float(h6), v1.w - __bfloat162float(h7));
            u32 off = (u32)(row * 128 + ((grp ^ (row & 7)) << 4));
            *(uint4*)(sm + AHI + off) = hq;
            *(uint4*)(sm + ALO + off) = lq;
        }
#pragma unroll
        for (int i = 0; i < 4; i++) {
            int g = tid + 256 * i;
            int row = g >> 3, grp = g & 7;
            size_t gix = (size_t)(nB + row) * K + kc + grp * 8;
            uint4 hv = *(const uint4*)(Whi + gix);
            uint4 lv = *(const uint4*)(Wlo + gix);
            u32 off = (u32)(row * 128 + ((grp ^ (row & 7)) << 4));
            *(uint4*)(sm + BHI + off) = hv;
            *(uint4*)(sm + BLO + off) = lv;
        }
        __syncthreads();

#pragma unroll
        for (int kt = 0; kt < 4; kt++) {
            u32 ah[2][4], al[2][4], bb[4][4];
#pragma unroll
            for (int mt = 0; mt < 2; mt++) {
                int sub = lane >> 3;
                int mrow = m0w + mt * 16 + (sub & 1) * 8 + (lane & 7);
                int c = kt * 2 + (sub >> 1);
                u32 ad = smb + mrow * 128 + ((u32)(c ^ (mrow & 7)) << 4);
                ldm_x4(ah[mt], ad + AHI);
                ldm_x4(al[mt], ad + ALO);
            }
            int subb = lane >> 3;
            u32 bad[4];
#pragma unroll
            for (int np = 0; np < 4; np++) {
                int nrow = n0w + np * 16 + (subb >> 1) * 8 + (lane & 7);
                int c = kt * 2 + (subb & 1);
                bad[np] = smb + nrow * 128 + ((u32)(c ^ (nrow & 7)) << 4);
                ldm_x4(bb[np], bad[np] + BHI);
            }
#pragma unroll
            for (int mt = 0; mt < 2; mt++)
#pragma unroll
                for (int nt = 0; nt < 8; nt++)
                    mma16816(acc[mt][nt], ah[mt], &bb[nt >> 1][(nt & 1) * 2]);
#pragma unroll
            for (int mt = 0; mt < 2; mt++)
#pragma unroll
                for (int nt = 0; nt < 8; nt++)
                    mma16816(acc[mt][nt], al[mt], &bb[nt >> 1][(nt & 1) * 2]);
#pragma unroll
            for (int np = 0; np < 4; np++)
                ldm_x4(bb[np], bad[np] + BLO);
#pragma unroll
            for (int mt = 0; mt < 2; mt++)
#pragma unroll
                for (int nt = 0; nt < 8; nt++)
                    mma16816(acc[mt][nt], ah[mt], &bb[nt >> 1][(nt & 1) * 2]);
        }
    }

#pragma unroll
    for (int mt = 0; mt < 2; mt++)
#pragma unroll
        for (int nt = 0; nt < 8; nt++) {
            int m = mB + m0w + mt * 16 + (lane >> 2);
            int n = nB + n0w + nt * 8 + (lane & 3) * 2;
            float2 bv = *(const float2*)&bias[n];
            float2 o0, o1;
            o0.x = acc[mt][nt][0] + bv.x;
            o0.y = acc[mt][nt][1] + bv.y;
            o1.x = acc[mt][nt][2] + bv.x;
            o1.y = acc[mt][nt][3] + bv.y;
            *(float2*)&out[(size_t)m * Gc + n] = o0;
            *(float2*)&out[(size_t)(m + 8) * Gc + n] = o1;
        }
}

// ============================================================
// LSTM recurrence, split-K over 512 threads:
// 1 CTA per 2 batches (128 CTAs). Thread (g = tid>>8, j = tid&255)
// owns rows {j, 256+j} restricted to k in [64g, 64g+64):
//   k [64g, 64g+32)    -> registers (32 u64 = 64 regs)
//   k [64g+32, 64g+64) -> smem (read once per step)
// Partials meet in gb; pointwise (threads < 256) sums the halves.
// ============================================================
#define REC_SMEM (2*8*512*16 + 2*2*128*4 + 2*2*512*4 + 256*4)  // 131072+2048+8192+1024

__global__ __launch_bounds__(512, 1) void lstm_rec(
    const float* __restrict__ xg, const float* __restrict__ whh,
    const float* __restrict__ h0, float* __restrict__ hout,
    const float* __restrict__ fcw, const float* __restrict__ fcb,
    float* __restrict__ outp, int is_l0)
{
    extern __shared__ char smraw[];
    ulonglong2* wsm = (ulonglong2*)smraw;            // [2 g][8 kq][512 rows]
    float* hs  = (float*)(smraw + 2 * 8 * 512 * 16); // [2 buf][2 batch][128]
    float* gb  = hs + 512;                           // [2 g][2 batch][512 rows]
    float* red = gb + 2048;                          // [256]

    const int tid = threadIdx.x;
    const int g = tid >> 8, j = tid & 255;
    const int b0 = blockIdx.x * 2;
    const int pb = (tid >> 7) & 1, p = tid & 127;    // pointwise mapping (tid<256)
    const int kb = g * 64;                            // group k-base

    // --- register weights: rows j, 256+j, k in [kb, kb+32) ---
    u64 wr0[16], wr1[16];
#pragma unroll
    for (int q = 0; q < 8; q++) {
        ulonglong2 t0 = *(const ulonglong2*)&whh[(size_t)j * Hc + kb + q * 4];
        wr0[2 * q] = t0.x; wr0[2 * q + 1] = t0.y;
        ulonglong2 t1 = *(const ulonglong2*)&whh[(size_t)(256 + j) * Hc + kb + q * 4];
        wr1[2 * q] = t1.x; wr1[2 * q + 1] = t1.y;
    }
    // --- smem weights: k in [kb+32, kb+64) ---
#pragma unroll
    for (int q = 0; q < 8; q++) {
        wsm[(g * 8 + q) * 512 + j] =
            *(const ulonglong2*)&whh[(size_t)j * Hc + kb + 32 + q * 4];
        wsm[(g * 8 + q) * 512 + 256 + j] =
            *(const ulonglong2*)&whh[(size_t)(256 + j) * Hc + kb + 32 + q * 4];
    }

    // --- init h (buffer 0), c = 0 ---
    if (tid < 256)
        hs[pb * 128 + p] = h0[(size_t)(b0 + pb) * Hc + p];
    float c = 0.f, hval = 0.f;

    const float* xA = xg + (size_t)b0 * Tc * Gc;
    const float* xB = xA + (size_t)Tc * Gc;
    float xa0 = 0.f, xa1 = 0.f, xb0 = 0.f, xb1 = 0.f;
    if (g == 0) {
        xa0 = __ldg(xA + j); xa1 = __ldg(xA + 256 + j);
        xb0 = __ldg(xB + j); xb1 = __ldg(xB + 256 + j);
    }
    __syncthreads();

#pragma unroll 1
    for (int t = 0; t < Tc; t++) {
        float na0, na1, nb0, nb1;
        if (g == 0) {
            size_t off = (size_t)((t + 1 < Tc) ? t + 1 : t) * Gc;
            na0 = __ldg(xA + off + j);       na1 = __ldg(xA + off + 256 + j);
            nb0 = __ldg(xB + off + j);       nb1 = __ldg(xB + off + 256 + j);
        }

        const float* hA = hs + (t & 1) * 256;
        const float* hB = hA + 128;
        u64 aA0 = 0, aB0 = 0, aA1 = 0, aB1 = 0;   // [row j / 256+j][batch A/B]
        // register half: k = kb + 4q
#pragma unroll
        for (int q = 0; q < 8; q++) {
            ulonglong2 ha = *(const ulonglong2*)(hA + kb + q * 4);
            ulonglong2 hb = *(const ulonglong2*)(hB + kb + q * 4);
            aA0 = ffma2(wr0[2*q], ha.x, aA0); aA0 = ffma2(wr0[2*q+1], ha.y, aA0);
            aB0 = ffma2(wr0[2*q], hb.x, aB0); aB0 = ffma2(wr0[2*q+1], hb.y, aB0);
            aA1 = ffma2(wr1[2*q], ha.x, aA1); aA1 = ffma2(wr1[2*q+1], ha.y, aA1);
            aB1 = ffma2(wr1[2*q], hb.x, aB1); aB1 = ffma2(wr1[2*q+1], hb.y, aB1);
        }
        // smem half: k = kb + 32 + 4q
#pragma unroll
        for (int q = 0; q < 8; q++) {
            ulonglong2 w0 = wsm[(g * 8 + q) * 512 + j];
            ulonglong2 w1 = wsm[(g * 8 + q) * 512 + 256 + j];
            ulonglong2 ha = *(const ulonglong2*)(hA + kb + 32 + q * 4);
            ulonglong2 hb = *(const ulonglong2*)(hB + kb + 32 + q * 4);
            aA0 = ffma2(w0.x, ha.x, aA0); aA0 = ffma2(w0.y, ha.y, aA0);
            aB0 = ffma2(w0.x, hb.x, aB0); aB0 = ffma2(w0.y, hb.y, aB0);
            aA1 = ffma2(w1.x, ha.x, aA1); aA1 = ffma2(w1.y, ha.y, aA1);
            aB1 = ffma2(w1.x, hb.x, aB1); aB1 = ffma2(w1.y, hb.y, aB1);
        }
        float pA0 = red2(aA0), pA1 = red2(aA1);
        float pB0 = red2(aB0), pB1 = red2(aB1);
        if (g == 0) { pA0 += xa0; pA1 += xa1; pB0 += xb0; pB1 += xb1; }
        gb[g * 1024 + j]             = pA0;
        gb[g * 1024 + 256 + j]       = pA1;
        gb[g * 1024 + 512 + j]       = pB0;
        gb[g * 1024 + 512 + 256 + j] = pB1;
        __syncthreads();

        // pointwise: threads < 256, (pb, p); sum the two k-half partials
        if (tid < 256) {
            float gi = gb[pb * 512 + p]       + gb[1024 + pb * 512 + p];
            float gf = gb[pb * 512 + 128 + p] + gb[1024 + pb * 512 + 128 + p];
            float gg = gb[pb * 512 + 256 + p] + gb[1024 + pb * 512 + 256 + p];
            float go = gb[pb * 512 + 384 + p] + gb[1024 + pb * 512 + 384 + p];
            float fI = sigf(gi), fF = sigf(gf), fG = tanh_f(gg), fO = sigf(go);
            c = fF * c + fI * fG;
            hval = fO * tanh_f(c);
            hs[((t + 1) & 1) * 256 + pb * 128 + p] = hval;
            if (is_l0)
                hout[((size_t)(b0 + pb) * Tc + t) * Hc + p] = hval;
        }
        if (g == 0) { xa0 = na0; xa1 = na1; xb0 = nb0; xb1 = nb1; }
        __syncthreads();
    }

    if (!is_l0) {
        if (tid < 256)
            red[pb * 128 + p] = hval * fcw[p];
        __syncthreads();
        if (tid < 2) {
            float s = fcb[0];
            for (int i = 0; i < 128; i++) s += red[tid * 128 + i];
            outp[b0 + tid] = s;
        }
    }
}

extern "C" void kernel_launch(void* const* d_in, const int* in_sizes, int n_in,
                              void* d_out, int out_size) {
    const float* x    = (const float*)d_in[0];
    const float* h0   = (const float*)d_in[1];
    const float* wih0 = (const float*)d_in[2];
    const float* whh0 = (const float*)d_in[3];
    const float* b0_  = (const float*)d_in[4];
    const float* wih1 = (const float*)d_in[5];
    const float* whh1 = (const float*)d_in[6];
    const float* b1_  = (const float*)d_in[7];
    const float* fcw  = (const float*)d_in[8];
    const float* fcb  = (const float*)d_in[9];
    float* out = (float*)d_out;

    cudaFuncSetAttribute(gemm_mma, cudaFuncAttributeMaxDynamicSharedMemorySize, GT_SMEM);
    cudaFuncSetAttribute(lstm_rec, cudaFuncAttributeMaxDynamicSharedMemorySize, REC_SMEM);

    float *xgp, *h0sp;
    cudaGetSymbolAddress((void**)&xgp, g_xg);
    cudaGetSymbolAddress((void**)&h0sp, g_h0s);
    __nv_bfloat16 *whi0, *wlo0, *whi1, *wlo1;
    cudaGetSymbolAddress((void**)&whi0, g_whi0);
    cudaGetSymbolAddress((void**)&wlo0, g_wlo0);
    cudaGetSymbolAddress((void**)&whi1, g_whi1);
    cudaGetSymbolAddress((void**)&wlo1, g_wlo1);

    // pre-convert input-GEMM weights to bf16 hi/lo
    conv_w<<<(Gc * 64 + 255) / 256, 256>>>(wih0, whi0, wlo0, Gc * 64);
    conv_w<<<(Gc * Hc + 255) / 256, 256>>>(wih1, whi1, wlo1, Gc * Hc);

    dim3 ggrid(Mc / 128, Gc / 128);
    // layer 0 (K=64)
    gemm_mma<<<ggrid, 256, GT_SMEM>>>(x, whi0, wlo0, b0_, xgp, 64);
    lstm_rec<<<Bc / 2, 512, REC_SMEM>>>(xgp, whh0, h0, h0sp,
                                        nullptr, nullptr, nullptr, 1);
    // layer 1 (K=128)
    gemm_mma<<<ggrid, 256, GT_SMEM>>>(h0sp, whi1, wlo1, b1_, xgp, 128);
    lstm_rec<<<Bc / 2, 512, REC_SMEM>>>(xgp, whh1, h0 + (size_t)Bc * Hc, nullptr,
                                        fcw, fcb, out, 0);
}